// round 7
// baseline (speedup 1.0000x reference)
#include <cuda_runtime.h>
#include <cstdint>

// Problem constants (x = [4096, 8192, 1] f32, G = 7)
constexpr int B_ROWS = 4096;
constexpr int I_COLS = 8192;
constexpr int G      = 7;

constexpr int BT   = 512;    // threads per block, 3 CTAs/SM
constexpr int NW   = 16;     // warps
constexpr int NB   = 384;    // quantile buckets (mean size ~21)
constexpr int NREP = 2;      // histogram replicas

// ---- dynamic shared memory layout (total ~71.8 KB -> 3 CTAs/SM) ----
constexpr size_t OFF_BUF  = 0;                                  // u64 buf[8192]   65536
constexpr size_t OFF_U    = OFF_BUF  + (size_t)I_COLS * 8;      // u32 U[NB]       1536
constexpr size_t OFF_HIST = OFF_U    + NB * 4;                  // u32 hist[2*NB]  3072
constexpr size_t OFF_BASE = OFF_HIST + NREP * NB * 4;           // u32 base[NB+1]
constexpr size_t OFF_CUR  = OFF_BASE + (NB + 1) * 4;            // u32 cursor[NB]
constexpr size_t OFF_AUX  = OFF_CUR  + NB * 4;                  // u32 aux[32]
constexpr size_t OFF_SCAL = OFF_AUX  + 32 * 4;                  // f32 scal[32]
constexpr size_t SMEM_BYTES = OFF_SCAL + 32 * 4;

// key transform: ascending u32 == descending float
__device__ __forceinline__ uint32_t kd(float f) {
    uint32_t b = __float_as_uint(f);
    uint32_t m = (uint32_t)(((int32_t)b) >> 31) | 0x80000000u;
    return ~(b ^ m);
}
__device__ __forceinline__ float inv_kd(uint32_t k) {
    uint32_t u = ~k;
    return __uint_as_float((u & 0x80000000u) ? (u ^ 0x80000000u) : ~u);
}

// bucket of x: MUFU-based guess from the sigmoid fit of Phi(x), corrected by
// an exact, monotone table walk (correctness depends only on the compares).
__device__ __forceinline__ int bucket_of(float x, uint32_t u, const uint32_t* __restrict__ U) {
    float z = fmaf(0.07056f * x * x, x, 1.5976f * x);
    int b = (int)((float)NB * __frcp_rn(1.0f + __expf(z)));   // ~ NB*(1-Phi(x))
    b = max(0, min(NB - 1, b));
    while (b < NB - 1 && u >= U[b]) ++b;
    while (b > 0 && u < U[b - 1]) --b;
    return b;
}

// ---------------- ascending bitonic sorts (warp-register) ----------------
template <int R>
__device__ __forceinline__ void bitonic32(uint32_t v[R], int lane) {
    constexpr int N = R * 32;
    #pragma unroll
    for (int k = 2; k <= N; k <<= 1) {
        #pragma unroll
        for (int j = k >> 1; j > 0; j >>= 1) {
            if (j >= 32) {
                const int jr = j >> 5;
                #pragma unroll
                for (int r = 0; r < R; r++) {
                    if ((r & jr) == 0) {
                        const int r2 = r + jr;
                        const int e  = r * 32 + lane;
                        const bool up = ((e & k) == 0);
                        uint32_t a = v[r], b = v[r2];
                        uint32_t lo = min(a, b), hi = max(a, b);
                        v[r]  = up ? lo : hi;
                        v[r2] = up ? hi : lo;
                    }
                }
            } else {
                #pragma unroll
                for (int r = 0; r < R; r++) {
                    const int e = r * 32 + lane;
                    uint32_t w = __shfl_xor_sync(0xFFFFFFFFu, v[r], j);
                    const bool up = ((e & k) == 0);
                    const bool keep_lo = (((e & j) == 0) == up);
                    v[r] = keep_lo ? min(v[r], w) : max(v[r], w);
                }
            }
        }
    }
}

template <int R>
__device__ __forceinline__ void bitonic64(unsigned long long v[R], int lane) {
    constexpr int N = R * 32;
    #pragma unroll
    for (int k = 2; k <= N; k <<= 1) {
        #pragma unroll
        for (int j = k >> 1; j > 0; j >>= 1) {
            if (j >= 32) {
                const int jr = j >> 5;
                #pragma unroll
                for (int r = 0; r < R; r++) {
                    if ((r & jr) == 0) {
                        const int r2 = r + jr;
                        const int e  = r * 32 + lane;
                        const bool up = ((e & k) == 0);
                        unsigned long long a = v[r], b = v[r2];
                        unsigned long long lo = a < b ? a : b;
                        unsigned long long hi = a < b ? b : a;
                        v[r]  = up ? lo : hi;
                        v[r2] = up ? hi : lo;
                    }
                }
            } else {
                #pragma unroll
                for (int r = 0; r < R; r++) {
                    const int e = r * 32 + lane;
                    unsigned long long w = __shfl_xor_sync(0xFFFFFFFFu, v[r], j);
                    const bool up = ((e & k) == 0);
                    const bool keep_lo = (((e & j) == 0) == up);
                    v[r] = keep_lo ? (v[r] < w ? v[r] : w) : (v[r] > w ? v[r] : w);
                }
            }
        }
    }
}

// narrow-bucket path: offset-packed u32 = (kd - lo)<<13 | idx  (order == (kd, idx))
template <int R>
__device__ __forceinline__ void sort_bucket_u32(
    const unsigned long long* __restrict__ buf, int start, int size, uint32_t lo,
    int lane, float* __restrict__ si, float* s_top, float* s_bot)
{
    const unsigned long long sub = (unsigned long long)lo << 13;
    uint32_t v[R];
    #pragma unroll
    for (int r = 0; r < R; r++) {
        int m = r * 32 + lane;
        v[r] = (m < size) ? (uint32_t)(buf[start + m] - sub) : 0xFFFFFFFFu;
    }
    bitonic32<R>(v, lane);
    #pragma unroll
    for (int r = 0; r < R; r++) {
        int m = r * 32 + lane;
        if (m < size) {
            int gr = start + m;                      // global descending rank
            si[gr] = (float)(v[r] & 8191u);
            if (gr < G || gr >= I_COLS - G) {
                float fv = inv_kd(lo + (v[r] >> 13));
                if (gr < G) s_top[gr] = fv;
                else        s_bot[gr - (I_COLS - G)] = fv;
            }
        }
    }
}

// wide-bucket path: full u64 packed (kd<<13 | idx)
template <int R>
__device__ __forceinline__ void sort_bucket_u64(
    const unsigned long long* __restrict__ buf, int start, int size, int lane,
    float* __restrict__ si, float* s_top, float* s_bot)
{
    unsigned long long v[R];
    #pragma unroll
    for (int r = 0; r < R; r++) {
        int m = r * 32 + lane;
        v[r] = (m < size) ? buf[start + m] : ~0ull;
    }
    bitonic64<R>(v, lane);
    #pragma unroll
    for (int r = 0; r < R; r++) {
        int m = r * 32 + lane;
        if (m < size) {
            unsigned long long p = v[r];
            int gr = start + m;
            si[gr] = (float)(unsigned)(p & 8191u);
            if (gr < G)           s_top[gr] = inv_kd((uint32_t)(p >> 13));
            if (gr >= I_COLS - G) s_bot[gr - (I_COLS - G)] = inv_kd((uint32_t)(p >> 13));
        }
    }
}

extern __shared__ unsigned char smem_raw[];

__global__ void __launch_bounds__(BT, 3)
portfolio_bucket_v3(const float* __restrict__ x, float* __restrict__ out)
{
    unsigned long long* buf    = (unsigned long long*)(smem_raw + OFF_BUF);
    uint32_t*           U      = (uint32_t*)(smem_raw + OFF_U);
    uint32_t*           hist   = (uint32_t*)(smem_raw + OFF_HIST);
    uint32_t*           base   = (uint32_t*)(smem_raw + OFF_BASE);
    uint32_t*           cursor = (uint32_t*)(smem_raw + OFF_CUR);
    uint32_t*           aux    = (uint32_t*)(smem_raw + OFF_AUX);
    float*              s_top  = (float*)(smem_raw + OFF_SCAL);   // [7]
    float*              s_bot  = s_top + 8;                       // [7]
    float*              s_win  = s_top + 16;                      // [7]
    float*              s_los  = s_top + 24;                      // [7]

    const int tid  = threadIdx.x;
    const int wid  = tid >> 5;
    const int lane = tid & 31;
    const int row  = blockIdx.x;

    const float*  xr  = x + (size_t)row * I_COLS;
    const float4* xr4 = (const float4*)xr;

    // ---- init: splitter table (exactly monotone) + zero hist ----
    if (tid < NB - 1) {
        float pi = (float)(tid + 1) * (1.0f / (float)NB);      // kd-space quantile
        float q  = 0.58754f * __logf((1.0f - pi) / pi);        // x-quantile (1-pi)
        U[tid] = kd(q);                                        // ascending in kd
    }
    if (tid == 0) { U[NB - 1] = 0xFFFFFFFFu; base[NB] = I_COLS; }
    if (tid < NREP * NB - BT) hist[BT + tid] = 0;
    hist[tid] = 0;
    __syncthreads();

    // ---- Phase 1: bucket each element, histogram (counts only) ----
    uint32_t* histw = hist + (wid & (NREP - 1)) * NB;
    #pragma unroll
    for (int q4 = 0; q4 < 4; q4++) {
        int vi = tid + q4 * BT;
        float4 xv = xr4[vi];
        atomicAdd(&histw[bucket_of(xv.x, kd(xv.x), U)], 1u);
        atomicAdd(&histw[bucket_of(xv.y, kd(xv.y), U)], 1u);
        atomicAdd(&histw[bucket_of(xv.z, kd(xv.z), U)], 1u);
        atomicAdd(&histw[bucket_of(xv.w, kd(xv.w), U)], 1u);
    }
    __syncthreads();

    // ---- Phase 2: reduce replicas + block exclusive scan -> base, cursor ----
    {
        uint32_t c = 0;
        if (tid < NB) {
            #pragma unroll
            for (int rep = 0; rep < NREP; rep++) c += hist[rep * NB + tid];
        }
        uint32_t inc = c;
        #pragma unroll
        for (int o = 1; o < 32; o <<= 1) {
            uint32_t n = __shfl_up_sync(0xFFFFFFFFu, inc, o);
            if (lane >= o) inc += n;
        }
        if (lane == 31) aux[wid] = inc;
        __syncthreads();
        if (wid == 0) {
            uint32_t t  = (lane < NW) ? aux[lane] : 0;
            uint32_t ti = t;
            #pragma unroll
            for (int o = 1; o < 32; o <<= 1) {
                uint32_t n = __shfl_up_sync(0xFFFFFFFFu, ti, o);
                if (lane >= o) ti += n;
            }
            if (lane < NW) aux[lane] = ti - t;      // exclusive warp prefix
        }
        __syncthreads();
        if (tid < NB) {
            uint32_t excl = aux[wid] + (inc - c);
            base[tid] = excl; cursor[tid] = excl;
        }
    }
    __syncthreads();

    // ---- Phase 3: recompute bucket, scatter packed (kd<<13 | idx) ----
    #pragma unroll
    for (int q4 = 0; q4 < 4; q4++) {
        int vi = tid + q4 * BT;
        float4 xv = xr4[vi];                        // L1/L2 re-hit
        uint32_t k0 = kd(xv.x), k1 = kd(xv.y), k2 = kd(xv.z), k3 = kd(xv.w);
        int b0 = bucket_of(xv.x, k0, U);
        int b1 = bucket_of(xv.y, k1, U);
        int b2 = bucket_of(xv.z, k2, U);
        int b3 = bucket_of(xv.w, k3, U);
        int e = vi * 4;
        uint32_t p0 = atomicAdd(&cursor[b0], 1u);
        buf[p0] = ((unsigned long long)k0 << 13) | (unsigned)(e + 0);
        uint32_t p1 = atomicAdd(&cursor[b1], 1u);
        buf[p1] = ((unsigned long long)k1 << 13) | (unsigned)(e + 1);
        uint32_t p2 = atomicAdd(&cursor[b2], 1u);
        buf[p2] = ((unsigned long long)k2 << 13) | (unsigned)(e + 2);
        uint32_t p3 = atomicAdd(&cursor[b3], 1u);
        buf[p3] = ((unsigned long long)k3 << 13) | (unsigned)(e + 3);
    }
    __syncthreads();

    // ---- b_c zero fill (independent; overlaps with sorts) ----
    float* bc = out + (size_t)row * I_COLS;
    float* si = out + (size_t)B_ROWS * I_COLS + (size_t)row * I_COLS;
    {
        float4 z = make_float4(0.f, 0.f, 0.f, 0.f);
        float4* bc4 = (float4*)bc;
        #pragma unroll
        for (int q4 = 0; q4 < 4; q4++) bc4[tid + q4 * BT] = z;
    }

    // ---- Phase 4: per-warp register bitonic sort of each bucket ----
    for (int b = wid; b < NB; b += NW) {
        int start = base[b];
        int size  = (int)base[b + 1] - start;
        if (size <= 0) continue;
        uint32_t lo = b ? U[b - 1] : 0u;
        bool narrow = (U[b] - lo) <= (1u << 19);
        if (narrow) {
            if      (size <= 32)  sort_bucket_u32<1>(buf, start, size, lo, lane, si, s_top, s_bot);
            else if (size <= 64)  sort_bucket_u32<2>(buf, start, size, lo, lane, si, s_top, s_bot);
            else if (size <= 128) sort_bucket_u32<4>(buf, start, size, lo, lane, si, s_top, s_bot);
            else goto fallback;
        } else {
            if      (size <= 32)  sort_bucket_u64<1>(buf, start, size, lane, si, s_top, s_bot);
            else if (size <= 64)  sort_bucket_u64<2>(buf, start, size, lane, si, s_top, s_bot);
            else if (size <= 128) sort_bucket_u64<4>(buf, start, size, lane, si, s_top, s_bot);
            else {
            fallback:
                // unconditional-correctness fallback (statistically unreachable)
                for (int m = lane; m < size; m += 32) {
                    unsigned long long p = buf[start + m];
                    int rank = 0;
                    for (int j = 0; j < size; j++) rank += (buf[start + j] < p);
                    int gr = start + rank;
                    si[gr] = (float)(unsigned)(p & 8191u);
                    if (gr < G)           s_top[gr] = inv_kd((uint32_t)(p >> 13));
                    if (gr >= I_COLS - G) s_bot[gr - (I_COLS - G)] = inv_kd((uint32_t)(p >> 13));
                }
            }
        }
    }
    __syncthreads();

    // ---- softmaxes ----
    if (tid == 0) {
        float m = s_top[0];
        #pragma unroll
        for (int i = 1; i < G; i++) m = fmaxf(m, s_top[i]);
        float e[G], s = 0.0f;
        #pragma unroll
        for (int i = 0; i < G; i++) { e[i] = expf(s_top[i] - m); s += e[i]; }
        float inv = 1.0f / s;
        #pragma unroll
        for (int i = 0; i < G; i++) s_win[i] = e[i] * inv;

        float m2 = 1.0f - s_bot[0];
        #pragma unroll
        for (int i = 1; i < G; i++) m2 = fmaxf(m2, 1.0f - s_bot[i]);
        float e2[G], s2 = 0.0f;
        #pragma unroll
        for (int i = 0; i < G; i++) { e2[i] = expf((1.0f - s_bot[i]) - m2); s2 += e2[i]; }
        float inv2 = 1.0f / s2;
        #pragma unroll
        for (int i = 0; i < G; i++) s_los[i] = -e2[i] * inv2;
    }
    __syncthreads();

    if (tid < G)          bc[tid] = s_win[tid];
    else if (tid < 2 * G) bc[I_COLS - G + (tid - G)] = s_los[tid - G];
}

extern "C" void kernel_launch(void* const* d_in, const int* in_sizes, int n_in,
                              void* d_out, int out_size)
{
    (void)in_sizes; (void)n_in; (void)out_size;
    const float* x = (const float*)d_in[0];
    float* out = (float*)d_out;

    cudaFuncSetAttribute(portfolio_bucket_v3,
                         cudaFuncAttributeMaxDynamicSharedMemorySize,
                         (int)SMEM_BYTES);
    portfolio_bucket_v3<<<B_ROWS, BT, SMEM_BYTES>>>(x, out);
}

// round 8
// speedup vs baseline: 1.1243x; 1.1243x over previous
#include <cuda_runtime.h>
#include <cstdint>

// Problem constants (x = [4096, 8192, 1] f32, G = 7)
constexpr int B_ROWS = 4096;
constexpr int I_COLS = 8192;
constexpr int G      = 7;

constexpr int BT = 512;      // threads per block, 3 CTAs/SM
constexpr int NW = 16;       // warps
constexpr int NB = 640;      // quantile buckets (mean size ~12.8)

// ---- dynamic shared memory layout (~74.2 KB -> 3 CTAs/SM) ----
constexpr size_t OFF_BUF  = 0;                               // u64 buf[8192] (also id-cache)
constexpr size_t OFF_U    = OFF_BUF  + (size_t)I_COLS * 8;   // u32 U[NB]
constexpr size_t OFF_HIST = OFF_U    + NB * 4;               // u32 hist[NB]
constexpr size_t OFF_BASE = OFF_HIST + NB * 4;               // u32 base[NB+1]
constexpr size_t OFF_CUR  = OFF_BASE + (NB + 1) * 4;         // u32 cursor[NB]
constexpr size_t OFF_AUX  = OFF_CUR  + NB * 4;               // u32 aux[16]
constexpr size_t OFF_SCAL = OFF_AUX  + 16 * 4;               // f32 scal[32]
constexpr size_t SMEM_BYTES = OFF_SCAL + 32 * 4;

// key transform: ascending u32 == descending float
__device__ __forceinline__ uint32_t kd(float f) {
    uint32_t b = __float_as_uint(f);
    uint32_t m = (uint32_t)(((int32_t)b) >> 31) | 0x80000000u;
    return ~(b ^ m);
}
__device__ __forceinline__ float inv_kd(uint32_t k) {
    uint32_t u = ~k;
    return __uint_as_float((u & 0x80000000u) ? (u ^ 0x80000000u) : ~u);
}

// bucket of x: MUFU-based guess from the sigmoid fit of Phi(x), corrected by
// an exact, monotone table walk (correctness depends only on the compares).
__device__ __forceinline__ int bucket_of(float x, uint32_t u, const uint32_t* __restrict__ U) {
    float z = fmaf(0.07056f * x * x, x, 1.5976f * x);
    int b = (int)((float)NB * __frcp_rn(1.0f + __expf(z)));   // ~ NB*(1-Phi(x))
    b = max(0, min(NB - 1, b));
    while (b < NB - 1 && u >= U[b]) ++b;
    while (b > 0 && u < U[b - 1]) --b;
    return b;
}

// ---------------- warp-register bitonic sorts (ascending) ----------------
template <int R>
__device__ __forceinline__ void bitonic32(uint32_t v[R], int lane) {
    constexpr int N = R * 32;
    #pragma unroll
    for (int k = 2; k <= N; k <<= 1) {
        #pragma unroll
        for (int j = k >> 1; j > 0; j >>= 1) {
            if (j >= 32) {
                const int jr = j >> 5;
                #pragma unroll
                for (int r = 0; r < R; r++) {
                    if ((r & jr) == 0) {
                        const int r2 = r + jr;
                        const int e  = r * 32 + lane;
                        const bool up = ((e & k) == 0);
                        uint32_t a = v[r], b = v[r2];
                        uint32_t lo = min(a, b), hi = max(a, b);
                        v[r]  = up ? lo : hi;
                        v[r2] = up ? hi : lo;
                    }
                }
            } else {
                #pragma unroll
                for (int r = 0; r < R; r++) {
                    const int e = r * 32 + lane;
                    uint32_t w = __shfl_xor_sync(0xFFFFFFFFu, v[r], j);
                    const bool up = ((e & k) == 0);
                    const bool keep_lo = (((e & j) == 0) == up);
                    v[r] = keep_lo ? min(v[r], w) : max(v[r], w);
                }
            }
        }
    }
}

template <int R>
__device__ __forceinline__ void bitonic64(unsigned long long v[R], int lane) {
    constexpr int N = R * 32;
    #pragma unroll
    for (int k = 2; k <= N; k <<= 1) {
        #pragma unroll
        for (int j = k >> 1; j > 0; j >>= 1) {
            if (j >= 32) {
                const int jr = j >> 5;
                #pragma unroll
                for (int r = 0; r < R; r++) {
                    if ((r & jr) == 0) {
                        const int r2 = r + jr;
                        const int e  = r * 32 + lane;
                        const bool up = ((e & k) == 0);
                        unsigned long long a = v[r], b = v[r2];
                        unsigned long long lo = a < b ? a : b;
                        unsigned long long hi = a < b ? b : a;
                        v[r]  = up ? lo : hi;
                        v[r2] = up ? hi : lo;
                    }
                }
            } else {
                #pragma unroll
                for (int r = 0; r < R; r++) {
                    const int e = r * 32 + lane;
                    unsigned long long w = __shfl_xor_sync(0xFFFFFFFFu, v[r], j);
                    const bool up = ((e & k) == 0);
                    const bool keep_lo = (((e & j) == 0) == up);
                    v[r] = keep_lo ? (v[r] < w ? v[r] : w) : (v[r] > w ? v[r] : w);
                }
            }
        }
    }
}

// 16-wide sub-warp sort of one bucket half (two buckets per warp), u32 packed
__device__ __forceinline__ void sort16_u32(
    const unsigned long long* __restrict__ buf, int start, int size, uint32_t lo,
    int m, float* __restrict__ si, float* s_top, float* s_bot)
{
    uint32_t v = (m < size) ? (uint32_t)(buf[start + m] - ((unsigned long long)lo << 13))
                            : 0xFFFFFFFFu;
    #pragma unroll
    for (int k = 2; k <= 16; k <<= 1) {
        #pragma unroll
        for (int j = k >> 1; j > 0; j >>= 1) {
            uint32_t w = __shfl_xor_sync(0xFFFFFFFFu, v, j, 16);
            const bool up = ((m & k) == 0);           // k=16: always ascending
            const bool keep_lo = (((m & j) == 0) == up);
            v = keep_lo ? min(v, w) : max(v, w);
        }
    }
    if (m < size) {
        int gr = start + m;
        si[gr] = (float)(v & 8191u);
        if (gr < G || gr >= I_COLS - G) {
            float fv = inv_kd(lo + (v >> 13));
            if (gr < G) s_top[gr] = fv;
            else        s_bot[gr - (I_COLS - G)] = fv;
        }
    }
}

// narrow-bucket 32-wide path: offset-packed u32 = (kd - lo)<<13 | idx
template <int R>
__device__ __forceinline__ void sort_bucket_u32(
    const unsigned long long* __restrict__ buf, int start, int size, uint32_t lo,
    int lane, float* __restrict__ si, float* s_top, float* s_bot)
{
    const unsigned long long sub = (unsigned long long)lo << 13;
    uint32_t v[R];
    #pragma unroll
    for (int r = 0; r < R; r++) {
        int m = r * 32 + lane;
        v[r] = (m < size) ? (uint32_t)(buf[start + m] - sub) : 0xFFFFFFFFu;
    }
    bitonic32<R>(v, lane);
    #pragma unroll
    for (int r = 0; r < R; r++) {
        int m = r * 32 + lane;
        if (m < size) {
            int gr = start + m;
            si[gr] = (float)(v[r] & 8191u);
            if (gr < G || gr >= I_COLS - G) {
                float fv = inv_kd(lo + (v[r] >> 13));
                if (gr < G) s_top[gr] = fv;
                else        s_bot[gr - (I_COLS - G)] = fv;
            }
        }
    }
}

// wide-bucket path: full u64 packed (kd<<13 | idx)
template <int R>
__device__ __forceinline__ void sort_bucket_u64(
    const unsigned long long* __restrict__ buf, int start, int size, int lane,
    float* __restrict__ si, float* s_top, float* s_bot)
{
    unsigned long long v[R];
    #pragma unroll
    for (int r = 0; r < R; r++) {
        int m = r * 32 + lane;
        v[r] = (m < size) ? buf[start + m] : ~0ull;
    }
    bitonic64<R>(v, lane);
    #pragma unroll
    for (int r = 0; r < R; r++) {
        int m = r * 32 + lane;
        if (m < size) {
            unsigned long long p = v[r];
            int gr = start + m;
            si[gr] = (float)(unsigned)(p & 8191u);
            if (gr < G)           s_top[gr] = inv_kd((uint32_t)(p >> 13));
            if (gr >= I_COLS - G) s_bot[gr - (I_COLS - G)] = inv_kd((uint32_t)(p >> 13));
        }
    }
}

// unconditional-correctness fallback (statistically unreachable)
__device__ void bucket_fallback(
    const unsigned long long* __restrict__ buf, int start, int size, int lane,
    float* __restrict__ si, float* s_top, float* s_bot)
{
    for (int m = lane; m < size; m += 32) {
        unsigned long long p = buf[start + m];
        int rank = 0;
        for (int j = 0; j < size; j++) rank += (buf[start + j] < p);
        int gr = start + rank;
        si[gr] = (float)(unsigned)(p & 8191u);
        if (gr < G)           s_top[gr] = inv_kd((uint32_t)(p >> 13));
        if (gr >= I_COLS - G) s_bot[gr - (I_COLS - G)] = inv_kd((uint32_t)(p >> 13));
    }
}

__device__ __forceinline__ void process_bucket(
    const unsigned long long* __restrict__ buf, int start, int size, uint32_t lo,
    bool narrow, int lane, float* __restrict__ si, float* s_top, float* s_bot)
{
    if (size <= 0) return;
    if (narrow) {
        if      (size <= 32)  sort_bucket_u32<1>(buf, start, size, lo, lane, si, s_top, s_bot);
        else if (size <= 64)  sort_bucket_u32<2>(buf, start, size, lo, lane, si, s_top, s_bot);
        else if (size <= 128) sort_bucket_u32<4>(buf, start, size, lo, lane, si, s_top, s_bot);
        else                  bucket_fallback(buf, start, size, lane, si, s_top, s_bot);
    } else {
        if      (size <= 32)  sort_bucket_u64<1>(buf, start, size, lane, si, s_top, s_bot);
        else if (size <= 64)  sort_bucket_u64<2>(buf, start, size, lane, si, s_top, s_bot);
        else if (size <= 128) sort_bucket_u64<4>(buf, start, size, lane, si, s_top, s_bot);
        else                  bucket_fallback(buf, start, size, lane, si, s_top, s_bot);
    }
}

extern __shared__ unsigned char smem_raw[];

__global__ void __launch_bounds__(BT, 3)
portfolio_bucket_v4(const float* __restrict__ x, float* __restrict__ out)
{
    unsigned long long* buf    = (unsigned long long*)(smem_raw + OFF_BUF);
    uint32_t*           U      = (uint32_t*)(smem_raw + OFF_U);
    uint32_t*           hist   = (uint32_t*)(smem_raw + OFF_HIST);
    uint32_t*           base   = (uint32_t*)(smem_raw + OFF_BASE);
    uint32_t*           cursor = (uint32_t*)(smem_raw + OFF_CUR);
    uint32_t*           aux    = (uint32_t*)(smem_raw + OFF_AUX);
    float*              s_top  = (float*)(smem_raw + OFF_SCAL);   // [7]
    float*              s_bot  = s_top + 8;                       // [7]
    float*              s_win  = s_top + 16;                      // [7]
    float*              s_los  = s_top + 24;                      // [7]

    const int tid  = threadIdx.x;
    const int wid  = tid >> 5;
    const int lane = tid & 31;
    const int row  = blockIdx.x;

    const float*  xr  = x + (size_t)row * I_COLS;
    const float4* xr4 = (const float4*)xr;

    // ---- init: splitter table (exactly monotone) + zero hist ----
    for (int i = tid; i < NB - 1; i += BT) {
        float pi = (float)(i + 1) * (1.0f / (float)NB);        // kd-space quantile
        float q  = 0.58754f * __logf((1.0f - pi) / pi);        // x-quantile (1-pi)
        U[i] = kd(q);                                          // ascending in kd
    }
    if (tid == 0) { U[NB - 1] = 0xFFFFFFFFu; base[NB] = I_COLS; }
    for (int i = tid; i < NB; i += BT) hist[i] = 0;
    __syncthreads();

    // ---- Phase 1: bucket each element; cache packed ids in (idle) buf ----
    #pragma unroll
    for (int q4 = 0; q4 < 4; q4++) {
        int vi = tid + q4 * BT;
        float4 xv = xr4[vi];
        int b0 = bucket_of(xv.x, kd(xv.x), U);
        int b1 = bucket_of(xv.y, kd(xv.y), U);
        int b2 = bucket_of(xv.z, kd(xv.z), U);
        int b3 = bucket_of(xv.w, kd(xv.w), U);
        buf[vi] = (unsigned long long)(uint32_t)(b0 | (b1 << 16))
                | ((unsigned long long)(uint32_t)(b2 | (b3 << 16)) << 32);
        atomicAdd(&hist[b0], 1u);
        atomicAdd(&hist[b1], 1u);
        atomicAdd(&hist[b2], 1u);
        atomicAdd(&hist[b3], 1u);
    }
    __syncthreads();

    // ---- Phase 2: exclusive scan over NB=640 (2 bins per thread) ----
    {
        uint32_t c0 = 0, c1 = 0, csum = 0;
        if (tid < NB / 2) { c0 = hist[2 * tid]; c1 = hist[2 * tid + 1]; csum = c0 + c1; }
        uint32_t inc = csum;
        #pragma unroll
        for (int o = 1; o < 32; o <<= 1) {
            uint32_t n = __shfl_up_sync(0xFFFFFFFFu, inc, o);
            if (lane >= o) inc += n;
        }
        if (lane == 31) aux[wid] = inc;
        __syncthreads();
        if (wid == 0) {
            uint32_t t  = (lane < NW) ? aux[lane] : 0;
            uint32_t ti = t;
            #pragma unroll
            for (int o = 1; o < 32; o <<= 1) {
                uint32_t n = __shfl_up_sync(0xFFFFFFFFu, ti, o);
                if (lane >= o) ti += n;
            }
            if (lane < NW) aux[lane] = ti - t;          // exclusive warp prefix
        }
        __syncthreads();
        if (tid < NB / 2) {
            uint32_t excl = aux[wid] + (inc - csum);
            base[2 * tid] = excl;      cursor[2 * tid] = excl;
            base[2 * tid + 1] = excl + c0; cursor[2 * tid + 1] = excl + c0;
        }
    }
    __syncthreads();

    // ---- Phase 3: read cached ids, then scatter packed (kd<<13 | idx) ----
    {
        unsigned long long idw[4];
        #pragma unroll
        for (int q4 = 0; q4 < 4; q4++) idw[q4] = buf[tid + q4 * BT];
        __syncthreads();                                 // ids read before overwrite
        #pragma unroll
        for (int q4 = 0; q4 < 4; q4++) {
            int vi = tid + q4 * BT;
            float4 xv = xr4[vi];                         // cache re-hit
            uint32_t k0 = kd(xv.x), k1 = kd(xv.y), k2 = kd(xv.z), k3 = kd(xv.w);
            unsigned long long w = idw[q4];
            int e = vi * 4;
            uint32_t p0 = atomicAdd(&cursor[(uint32_t)w & 0xFFFFu], 1u);
            buf[p0] = ((unsigned long long)k0 << 13) | (unsigned)(e + 0);
            uint32_t p1 = atomicAdd(&cursor[(uint32_t)(w >> 16) & 0xFFFFu], 1u);
            buf[p1] = ((unsigned long long)k1 << 13) | (unsigned)(e + 1);
            uint32_t p2 = atomicAdd(&cursor[(uint32_t)(w >> 32) & 0xFFFFu], 1u);
            buf[p2] = ((unsigned long long)k2 << 13) | (unsigned)(e + 2);
            uint32_t p3 = atomicAdd(&cursor[(uint32_t)(w >> 48) & 0xFFFFu], 1u);
            buf[p3] = ((unsigned long long)k3 << 13) | (unsigned)(e + 3);
        }
    }
    __syncthreads();

    // ---- b_c zero fill (independent; overlaps with sorts) ----
    float* bc = out + (size_t)row * I_COLS;
    float* si = out + (size_t)B_ROWS * I_COLS + (size_t)row * I_COLS;
    {
        float4 z = make_float4(0.f, 0.f, 0.f, 0.f);
        float4* bc4 = (float4*)bc;
        #pragma unroll
        for (int q4 = 0; q4 < 4; q4++) bc4[tid + q4 * BT] = z;
    }

    // ---- Phase 4: two buckets per warp (16-wide nets) where possible ----
    for (int pb = wid; pb < NB / 2; pb += NW) {
        int b0 = 2 * pb, b1 = b0 + 1;
        int st0 = base[b0], st1 = base[b1], end1 = base[b1 + 1];
        int s0 = st1 - st0, s1 = end1 - st1;
        uint32_t lo0 = b0 ? U[b0 - 1] : 0u;
        uint32_t lo1 = U[b0];
        bool nar0 = (U[b0] - lo0) <= (1u << 19);
        bool nar1 = (U[b1] - lo1) <= (1u << 19);
        if (s0 <= 16 && s1 <= 16 && nar0 && nar1) {
            const int half = lane >> 4, m = lane & 15;
            sort16_u32(buf, half ? st1 : st0, half ? s1 : s0,
                       half ? lo1 : lo0, m, si, s_top, s_bot);
        } else {
            process_bucket(buf, st0, s0, lo0, nar0, lane, si, s_top, s_bot);
            process_bucket(buf, st1, s1, lo1, nar1, lane, si, s_top, s_bot);
        }
    }
    __syncthreads();

    // ---- softmaxes ----
    if (tid == 0) {
        float m = s_top[0];
        #pragma unroll
        for (int i = 1; i < G; i++) m = fmaxf(m, s_top[i]);
        float e[G], s = 0.0f;
        #pragma unroll
        for (int i = 0; i < G; i++) { e[i] = expf(s_top[i] - m); s += e[i]; }
        float inv = 1.0f / s;
        #pragma unroll
        for (int i = 0; i < G; i++) s_win[i] = e[i] * inv;

        float m2 = 1.0f - s_bot[0];
        #pragma unroll
        for (int i = 1; i < G; i++) m2 = fmaxf(m2, 1.0f - s_bot[i]);
        float e2[G], s2 = 0.0f;
        #pragma unroll
        for (int i = 0; i < G; i++) { e2[i] = expf((1.0f - s_bot[i]) - m2); s2 += e2[i]; }
        float inv2 = 1.0f / s2;
        #pragma unroll
        for (int i = 0; i < G; i++) s_los[i] = -e2[i] * inv2;
    }
    __syncthreads();

    if (tid < G)          bc[tid] = s_win[tid];
    else if (tid < 2 * G) bc[I_COLS - G + (tid - G)] = s_los[tid - G];
}

extern "C" void kernel_launch(void* const* d_in, const int* in_sizes, int n_in,
                              void* d_out, int out_size)
{
    (void)in_sizes; (void)n_in; (void)out_size;
    const float* x = (const float*)d_in[0];
    float* out = (float*)d_out;

    cudaFuncSetAttribute(portfolio_bucket_v4,
                         cudaFuncAttributeMaxDynamicSharedMemorySize,
                         (int)SMEM_BYTES);
    portfolio_bucket_v4<<<B_ROWS, BT, SMEM_BYTES>>>(x, out);
}